// round 11
// baseline (speedup 1.0000x reference)
#include <cuda_runtime.h>
#include <cuda_fp16.h>

// ---------------------------------------------------------------------------
// R11: HMMA ConvLSTM, fp16 single-pass, NB=8; scatter replaced by
// compact-h buffer + vectorized 64B row copies (B k-order = tap*32+ch).
// CTA = 8 batches (n=128), 512 threads = 16 warps: warp (T, nh) covers
// A-rows [32T,32T+32) x n-cols [32nh,32nh+32).
// A row permutation: R = 32T + 8g + q <-> oc = g*32 + (8T+q) (g=gate)
// => each lane holds all 4 gates of channel ch=8T+q: LSTM fully in-lane.
// ---------------------------------------------------------------------------

typedef unsigned int u32;
typedef unsigned short u16;

#define NTHR 512
#define NB   8

#define AHI_OFF 0            // 128 x 640B = 81920
#define BHI_OFF 81920        // 128 x 640B = 81920 (alias: hfin/z1/z2 after t=11)
#define HC_OFF  163840       // h-compact [128 n][32 ch] u16 = 8192
#define XS_OFF  172032       // 12*8*48 u16 = 9216
#define HF_OFF  181248       // 8*32 f32 = 1024
#define SMEM_TOT 182272

static __device__ __forceinline__ u32 sw640(u32 b) { return b ^ ((b >> 3) & 0x70); }

static __device__ __forceinline__ u32 smem_u32(const void* p) {
    u32 a;
    asm("{ .reg .u64 t; cvta.to.shared.u64 t, %1; cvt.u32.u64 %0, t; }" : "=r"(a) : "l"(p));
    return a;
}
static __device__ __forceinline__ float sigf(float v) {
    return __fdividef(1.0f, 1.0f + __expf(-v));
}
static __device__ __forceinline__ float tanh_fast(float v) {
    v = fminf(fmaxf(v, -15.0f), 15.0f);
    float e = __expf(2.0f * v);
    return __fdividef(e - 1.0f, e + 1.0f);
}
static __device__ __forceinline__ void ldsm4(u32& r0, u32& r1, u32& r2, u32& r3, u32 a) {
    asm volatile("ldmatrix.sync.aligned.m8n8.x4.shared.b16 {%0,%1,%2,%3}, [%4];"
        : "=r"(r0), "=r"(r1), "=r"(r2), "=r"(r3) : "r"(a));
}
static __device__ __forceinline__ void mma16816(float* d, u32 a0, u32 a1, u32 a2, u32 a3,
                                                u32 b0, u32 b1) {
    asm volatile("mma.sync.aligned.m16n8k16.row.col.f32.f16.f16.f32 "
        "{%0,%1,%2,%3}, {%4,%5,%6,%7}, {%8,%9}, {%0,%1,%2,%3};"
        : "+f"(d[0]), "+f"(d[1]), "+f"(d[2]), "+f"(d[3])
        : "r"(a0), "r"(a1), "r"(a2), "r"(a3), "r"(b0), "r"(b1));
}

extern __shared__ char smc[];

__global__ __launch_bounds__(NTHR, 1)
void wq_hmma4_kernel(const float* __restrict__ x,      const float* __restrict__ hour,
                     const float* __restrict__ conv_w, const float* __restrict__ conv_b,
                     const float* __restrict__ he_w1,  const float* __restrict__ he_b1,
                     const float* __restrict__ he_w2,  const float* __restrict__ he_b2,
                     const float* __restrict__ d_w1,   const float* __restrict__ d_b1,
                     const float* __restrict__ d_w2,   const float* __restrict__ d_b2,
                     const float* __restrict__ d_w3,   const float* __restrict__ d_b3,
                     float* __restrict__ out, int B)
{
    const int tid  = threadIdx.x;
    const int w    = tid >> 5, lane = tid & 31;
    const int T    = w >> 2, nh = w & 3;
    const int q    = lane >> 2, j = lane & 3;
    const int b0   = blockIdx.x * NB;
    const u32 sb   = smem_u32(smc);
    u16* xs = (u16*)(smc + XS_OFF);

    // ---------------- prologue ----------------
    {   // zero BHI (81920 B = 20480 u32)
        u32* bz = (u32*)(smc + BHI_OFF);
        #pragma unroll
        for (int i = 0; i < 40; i++) bz[tid + i * NTHR] = 0u;
    }
    for (int e = tid; e < 12 * NB * 48; e += NTHR) {       // 4608
        int t = e / 384, rm = e - t * 384;
        int bb = rm / 48, qq = rm - bb * 48;
        int gb = b0 + bb; if (gb >= B) gb = B - 1;
        xs[e] = __half_as_ushort(__float2half(x[(size_t)gb * 576 + t * 48 + qq]));
    }
    for (int e = tid; e < 128 * 320; e += NTHR) {          // A build: 80/thread
        int R = e / 320, k = e - R * 320;
        int g = (R >> 3) & 3, TT = R >> 5, qq = R & 7;
        int oc = g * 32 + TT * 8 + qq;
        float wv = 0.0f;
        if (k < 288)      wv = conv_w[oc * 315 + (3 + (k & 31)) * 9 + (k >> 5)];
        else if (k < 315) { int m = k - 288; wv = conv_w[oc * 315 + (m % 3) * 9 + (m / 3)]; }
        *(u16*)(smc + AHI_OFF + sw640((u32)(R * 640 + k * 2))) =
            __half_as_ushort(__float2half(wv));
    }
    __syncthreads();

    // x scatter for t=0 (k = 288 + tap*3 + xc)
    if (tid < NB * 48) {
        int bb = tid / 48, m = tid - bb * 48;
        int xc = m >> 4, sy = (m >> 2) & 3, sx = m & 3;
        u16 hv = xs[bb * 48 + m];
        #pragma unroll
        for (int dy = 0; dy < 3; dy++) {
            int ny = sy + 1 - dy; if (ny < 0 || ny > 3) continue;
            #pragma unroll
            for (int dx = 0; dx < 3; dx++) {
                int nx = sx + 1 - dx; if (nx < 0 || nx > 3) continue;
                int k = 288 + (dy * 3 + dx) * 3 + xc;
                int n2 = bb * 16 + ny * 4 + nx;
                *(u16*)(smc + BHI_OFF + sw640((u32)(n2 * 640 + k * 2))) = hv;
            }
        }
    }

    // per-lane fragment raw offsets
    const u32 araw0 = (u32)((32 * T + (lane & 7) + ((lane >> 3) & 1) * 8) * 640
                            + ((lane >> 4) & 1) * 16);
    const u32 araw1 = araw0 + 16 * 640;
    const int rB0   = 32 * nh + (lane & 7) + ((lane >> 4) & 1) * 8;
    const int rB1   = rB0 + 16;
    const u32 kbB   = (u32)(((lane >> 3) & 1) * 16);
    const u32 braw0 = (u32)(rB0 * 640) + kbB;
    const u32 braw1 = (u32)(rB1 * 640) + kbB;

    // per-lane biases: channel ch = 8T+q, gates i,f,o,g
    const int ch = 8 * T + q;
    const float bI = conv_b[ch], bF = conv_b[32 + ch];
    const float bO = conv_b[64 + ch], bG = conv_b[96 + ch];

    // copy-phase constants: thread covers (n2 = tid>>2, u = tid&3)
    const int n2c = tid >> 2, ucp = tid & 3;
    const int pyc = (n2c >> 2) & 3, pxc = n2c & 3;
    const int hrow_base = (n2c >> 4) << 4;     // bb*16

    float cst[8];
    #pragma unroll
    for (int i = 0; i < 8; i++) cst[i] = 0.0f;

    float* hfin = (float*)(smc + BHI_OFF);               // [512][8] after t=11

    __syncthreads();

    // ---------------------- 12-step recurrence ----------------------
    #pragma unroll 1
    for (int t = 0; t < 12; ++t) {
        float accA[4][4], accB[4][4];                    // [nf][d]; frag0 (i,f), frag1 (o,g)
        #pragma unroll
        for (int nf = 0; nf < 4; nf++) {
            accA[nf][0] = bI; accA[nf][1] = bI; accA[nf][2] = bF; accA[nf][3] = bF;
            accB[nf][0] = bO; accB[nf][1] = bO; accB[nf][2] = bG; accB[nf][3] = bG;
        }

        #pragma unroll 2
        for (int s = 0; s < 20; ++s) {
            const u32 so = (u32)(s * 32);
            u32 a0,a1,a2,a3, a4,a5,a6,a7, p0,p1,p2,p3, p4,p5,p6,p7;
            ldsm4(a0,a1,a2,a3, sb + AHI_OFF + sw640(araw0 + so));
            ldsm4(a4,a5,a6,a7, sb + AHI_OFF + sw640(araw1 + so));
            ldsm4(p0,p1,p2,p3, sb + BHI_OFF + sw640(braw0 + so));
            ldsm4(p4,p5,p6,p7, sb + BHI_OFF + sw640(braw1 + so));
            mma16816(accA[0], a0,a1,a2,a3, p0,p1);
            mma16816(accA[1], a0,a1,a2,a3, p2,p3);
            mma16816(accA[2], a0,a1,a2,a3, p4,p5);
            mma16816(accA[3], a0,a1,a2,a3, p6,p7);
            mma16816(accB[0], a4,a5,a6,a7, p0,p1);
            mma16816(accB[1], a4,a5,a6,a7, p2,p3);
            mma16816(accB[2], a4,a5,a6,a7, p4,p5);
            mma16816(accB[3], a4,a5,a6,a7, p6,p7);
        }

        __syncthreads();   // all ldmatrix reads done

        // ---- LSTM cell (in-lane) -> h-compact [n][ch] (or hfin at t=11) ----
        #pragma unroll
        for (int nf = 0; nf < 4; nf++) {
            #pragma unroll
            for (int cc = 0; cc < 2; cc++) {
                float gi = accA[nf][cc],     gf = accA[nf][2 + cc];
                float go = accB[nf][cc],     gg = accB[nf][2 + cc];
                const int ci = nf * 2 + cc;
                float c = sigf(gf) * cst[ci] + sigf(gi) * tanh_fast(gg);
                cst[ci] = c;
                float h = sigf(go) * tanh_fast(c);

                const int n = nh * 32 + nf * 8 + 2 * j + cc;
                if (t < 11) {
                    u32 myh = (u32)__half_as_ushort(__float2half(h));
                    u32 oth = __shfl_down_sync(0xFFFFFFFFu, myh, 4);
                    if ((q & 1) == 0)      // ch even: pack (ch, ch+1)
                        *(u32*)(smc + HC_OFF + n * 64 + ch * 2) = myh | (oth << 16);
                } else {
                    hfin[(ch * 16 + (n & 15)) * 8 + (n >> 4)] = h;
                }
            }
        }

        if (t < 11) {
            __syncthreads();   // h-compact ready

            // ---- vector copy: B[n2][tap*32 .. +32) = hc[nsrc][0..32) ----
            #pragma unroll
            for (int tap = 0; tap < 9; tap++) {
                const int dy = tap / 3 - 1, dx = tap % 3 - 1;
                const int sy = pyc + dy, sx = pxc + dx;
                if (sy >= 0 && sy < 4 && sx >= 0 && sx < 4) {
                    const int nsrc = hrow_base + (sy << 2) + sx;
                    uint4 v = *(const uint4*)(smc + HC_OFF + nsrc * 64 + ucp * 16);
                    *(uint4*)(smc + BHI_OFF +
                              sw640((u32)(n2c * 640 + tap * 64 + ucp * 16))) = v;
                }
            }

            // x scatter for t+1
            if (tid < NB * 48) {
                int bb = tid / 48, m = tid - bb * 48;
                int xc = m >> 4, sy2 = (m >> 2) & 3, sx2 = m & 3;
                u16 hv = xs[(t + 1) * 384 + bb * 48 + m];
                #pragma unroll
                for (int dy = 0; dy < 3; dy++) {
                    int ny = sy2 + 1 - dy; if (ny < 0 || ny > 3) continue;
                    #pragma unroll
                    for (int dx = 0; dx < 3; dx++) {
                        int nx = sx2 + 1 - dx; if (nx < 0 || nx > 3) continue;
                        int k = 288 + (dy * 3 + dx) * 3 + xc;
                        int nn = bb * 16 + ny * 4 + nx;
                        *(u16*)(smc + BHI_OFF + sw640((u32)(nn * 640 + k * 2))) = hv;
                    }
                }
            }
            __syncthreads();   // B ready for next mma
        }
    }

    __syncthreads();           // hfin visible to all

    // ------------------------------ decoder ------------------------------
    float* hf_s = (float*)(smc + HF_OFF);                 // [8][32]
    float* z1   = (float*)(smc + BHI_OFF + 16384);        // [256][8]
    float* z2   = (float*)(smc + BHI_OFF + 24576);        // [128][8]
    const int db = tid >> 6, dt = tid & 63;
    const int gb = b0 + db;
    const int gld = (gb < B) ? gb : (B - 1);

    if (dt < 32) {
        float hv = hour[gld];
        float a = he_b2[dt];
        #pragma unroll
        for (int k2 = 0; k2 < 16; ++k2) {
            float tt = fmaxf(hv * he_w1[k2] + he_b1[k2], 0.0f);
            a += tt * he_w2[k2 * 32 + dt];
        }
        hf_s[db * 32 + dt] = a;
    }
    __syncthreads();

    // L1: 544 -> 256, 4 outputs/thread
    {
        const int j0 = dt * 4;
        float a0 = d_b1[j0], a1 = d_b1[j0 + 1], a2 = d_b1[j0 + 2], a3 = d_b1[j0 + 3];
        #pragma unroll 4
        for (int i = 0; i < 512; ++i) {
            float zi = hfin[i * 8 + db];
            float4 w4 = *(const float4*)(d_w1 + i * 256 + j0);
            a0 += zi * w4.x; a1 += zi * w4.y; a2 += zi * w4.z; a3 += zi * w4.w;
        }
        #pragma unroll 4
        for (int i = 0; i < 32; ++i) {
            float zi = hf_s[db * 32 + i];
            float4 w4 = *(const float4*)(d_w1 + (512 + i) * 256 + j0);
            a0 += zi * w4.x; a1 += zi * w4.y; a2 += zi * w4.z; a3 += zi * w4.w;
        }
        __syncthreads();       // hfin reads done before z1 writes overlap region
        z1[(j0 + 0) * 8 + db] = fmaxf(a0, 0.0f);
        z1[(j0 + 1) * 8 + db] = fmaxf(a1, 0.0f);
        z1[(j0 + 2) * 8 + db] = fmaxf(a2, 0.0f);
        z1[(j0 + 3) * 8 + db] = fmaxf(a3, 0.0f);
    }
    __syncthreads();

    // L2: 256 -> 128, 2 outputs/thread
    {
        const int j0 = dt * 2;
        float a0 = d_b2[j0], a1 = d_b2[j0 + 1];
        #pragma unroll 4
        for (int i = 0; i < 256; ++i) {
            float zi = z1[i * 8 + db];
            float2 w2 = *(const float2*)(d_w2 + i * 128 + j0);
            a0 += zi * w2.x; a1 += zi * w2.y;
        }
        z2[(j0 + 0) * 8 + db] = fmaxf(a0, 0.0f);
        z2[(j0 + 1) * 8 + db] = fmaxf(a1, 0.0f);
    }
    __syncthreads();

    // L3: 128 -> 30 + sigmoid
    if (dt < 30 && gb < B) {
        float a = d_b3[dt];
        #pragma unroll 4
        for (int i = 0; i < 128; ++i)
            a += z2[i * 8 + db] * d_w3[i * 30 + dt];
        out[(size_t)gb * 30 + dt] = sigf(a);
    }
}

extern "C" void kernel_launch(void* const* d_in, const int* in_sizes, int n_in,
                              void* d_out, int out_size)
{
    const float* x      = (const float*)d_in[0];
    const float* hour   = (const float*)d_in[1];
    const float* conv_w = (const float*)d_in[2];
    const float* conv_b = (const float*)d_in[3];
    const float* he_w1  = (const float*)d_in[4];
    const float* he_b1  = (const float*)d_in[5];
    const float* he_w2  = (const float*)d_in[6];
    const float* he_b2  = (const float*)d_in[7];
    const float* d_w1   = (const float*)d_in[8];
    const float* d_b1   = (const float*)d_in[9];
    const float* d_w2   = (const float*)d_in[10];
    const float* d_b2   = (const float*)d_in[11];
    const float* d_w3   = (const float*)d_in[12];
    const float* d_b3   = (const float*)d_in[13];

    const int B    = in_sizes[0] / 576;
    const int grid = (B + NB - 1) / NB;

    cudaFuncSetAttribute(wq_hmma4_kernel,
                         cudaFuncAttributeMaxDynamicSharedMemorySize, SMEM_TOT);

    wq_hmma4_kernel<<<grid, NTHR, SMEM_TOT>>>(x, hour, conv_w, conv_b,
                                              he_w1, he_b1, he_w2, he_b2,
                                              d_w1, d_b1, d_w2, d_b2, d_w3, d_b3,
                                              (float*)d_out, B);
}

// round 12
// speedup vs baseline: 1.0525x; 1.0525x over previous
#include <cuda_runtime.h>
#include <cuda_fp16.h>

// ---------------------------------------------------------------------------
// R12: HMMA ConvLSTM, fp16 single-pass, NB=8, phase-shifted half-CTAs.
// Half H (warps 8H..8H+7, 256 threads) owns batches [4H,4H+4) = B-rows
// [64H, 64H+64), with its own named barrier (1+H). Halves share read-only A.
// A one-time stagger (bar.arrive/bar.sync id 3) offsets the halves so one
// half's tensor/ldsm phase overlaps the other's MUFU cell phase.
// Warp (half, T, nhl): A-rows [32T,32T+32) x n-cols [64H+32nhl, +32).
// A row perm: R = 32T + 8g + q <-> oc = g*32 + (8T+q): LSTM fully in-lane.
// ---------------------------------------------------------------------------

typedef unsigned int u32;
typedef unsigned short u16;

#define NTHR 512
#define NB   8

#define AHI_OFF  0           // 128 x 640B = 81920
#define BHI_OFF  81920       // 128 x 640B = 81920 (alias: z1/z2 after loop)
#define HC_OFF   163840      // h-compact [128 n][32 ch] u16 = 8192
#define XS_OFF   172032      // 12*8*48 u16 = 9216
#define HF_OFF   181248      // 8*32 f32 = 1024
#define HFIN_OFF 182272      // [512][8] f32 = 16384 (dedicated, NOT aliasing B)
#define SMEM_TOT 198656

static __device__ __forceinline__ u32 sw640(u32 b) { return b ^ ((b >> 3) & 0x70); }

static __device__ __forceinline__ u32 smem_u32(const void* p) {
    u32 a;
    asm("{ .reg .u64 t; cvta.to.shared.u64 t, %1; cvt.u32.u64 %0, t; }" : "=r"(a) : "l"(p));
    return a;
}
static __device__ __forceinline__ float sigf(float v) {
    return __fdividef(1.0f, 1.0f + __expf(-v));
}
static __device__ __forceinline__ float tanh_fast(float v) {
    v = fminf(fmaxf(v, -15.0f), 15.0f);
    float e = __expf(2.0f * v);
    return __fdividef(e - 1.0f, e + 1.0f);
}
static __device__ __forceinline__ void ldsm4(u32& r0, u32& r1, u32& r2, u32& r3, u32 a) {
    asm volatile("ldmatrix.sync.aligned.m8n8.x4.shared.b16 {%0,%1,%2,%3}, [%4];"
        : "=r"(r0), "=r"(r1), "=r"(r2), "=r"(r3) : "r"(a));
}
static __device__ __forceinline__ void mma16816(float* d, u32 a0, u32 a1, u32 a2, u32 a3,
                                                u32 b0, u32 b1) {
    asm volatile("mma.sync.aligned.m16n8k16.row.col.f32.f16.f16.f32 "
        "{%0,%1,%2,%3}, {%4,%5,%6,%7}, {%8,%9}, {%0,%1,%2,%3};"
        : "+f"(d[0]), "+f"(d[1]), "+f"(d[2]), "+f"(d[3])
        : "r"(a0), "r"(a1), "r"(a2), "r"(a3), "r"(b0), "r"(b1));
}
static __device__ __forceinline__ void barh(int id) {       // per-half barrier
    asm volatile("bar.sync %0, 256;" :: "r"(id) : "memory");
}

extern __shared__ char smc[];

__global__ __launch_bounds__(NTHR, 1)
void wq_hmma5_kernel(const float* __restrict__ x,      const float* __restrict__ hour,
                     const float* __restrict__ conv_w, const float* __restrict__ conv_b,
                     const float* __restrict__ he_w1,  const float* __restrict__ he_b1,
                     const float* __restrict__ he_w2,  const float* __restrict__ he_b2,
                     const float* __restrict__ d_w1,   const float* __restrict__ d_b1,
                     const float* __restrict__ d_w2,   const float* __restrict__ d_b2,
                     const float* __restrict__ d_w3,   const float* __restrict__ d_b3,
                     float* __restrict__ out, int B)
{
    const int tid  = threadIdx.x;
    const int w    = tid >> 5, lane = tid & 31;
    const int half = w >> 3;                 // 0 or 1
    const int wh   = w & 7;                  // warp within half
    const int T    = wh >> 1, nhl = wh & 1;  // T 0..3, nhl 0..1
    const int q    = lane >> 2, j = lane & 3;
    const int b0   = blockIdx.x * NB;
    const int tid_h = tid & 255;             // thread within half
    const u32 sb   = smem_u32(smc);
    u16* xs = (u16*)(smc + XS_OFF);

    // ---------------- prologue (all threads, global syncs) ----------------
    {   // zero BHI (81920 B = 20480 u32)
        u32* bz = (u32*)(smc + BHI_OFF);
        #pragma unroll
        for (int i = 0; i < 40; i++) bz[tid + i * NTHR] = 0u;
    }
    for (int e = tid; e < 12 * NB * 48; e += NTHR) {       // 4608
        int t = e / 384, rm = e - t * 384;
        int bb = rm / 48, qq = rm - bb * 48;
        int gb = b0 + bb; if (gb >= B) gb = B - 1;
        xs[e] = __half_as_ushort(__float2half(x[(size_t)gb * 576 + t * 48 + qq]));
    }
    for (int e = tid; e < 128 * 320; e += NTHR) {          // A build: 80/thread
        int R = e / 320, k = e - R * 320;
        int g = (R >> 3) & 3, TT = R >> 5, qq = R & 7;
        int oc = g * 32 + TT * 8 + qq;
        float wv = 0.0f;
        if (k < 288)      wv = conv_w[oc * 315 + (3 + (k & 31)) * 9 + (k >> 5)];
        else if (k < 315) { int m = k - 288; wv = conv_w[oc * 315 + (m % 3) * 9 + (m / 3)]; }
        *(u16*)(smc + AHI_OFF + sw640((u32)(R * 640 + k * 2))) =
            __half_as_ushort(__float2half(wv));
    }
    __syncthreads();

    // x scatter for t=0
    if (tid < NB * 48) {
        int bb = tid / 48, m = tid - bb * 48;
        int xc = m >> 4, sy = (m >> 2) & 3, sx = m & 3;
        u16 hv = xs[bb * 48 + m];
        #pragma unroll
        for (int dy = 0; dy < 3; dy++) {
            int ny = sy + 1 - dy; if (ny < 0 || ny > 3) continue;
            #pragma unroll
            for (int dx = 0; dx < 3; dx++) {
                int nx = sx + 1 - dx; if (nx < 0 || nx > 3) continue;
                int k = 288 + (dy * 3 + dx) * 3 + xc;
                int n2 = bb * 16 + ny * 4 + nx;
                *(u16*)(smc + BHI_OFF + sw640((u32)(n2 * 640 + k * 2))) = hv;
            }
        }
    }

    // per-lane fragment raw offsets
    const u32 araw0 = (u32)((32 * T + (lane & 7) + ((lane >> 3) & 1) * 8) * 640
                            + ((lane >> 4) & 1) * 16);
    const u32 araw1 = araw0 + 16 * 640;
    const int rB0   = half * 64 + 32 * nhl + (lane & 7) + ((lane >> 4) & 1) * 8;
    const int rB1   = rB0 + 16;
    const u32 kbB   = (u32)(((lane >> 3) & 1) * 16);
    const u32 braw0 = (u32)(rB0 * 640) + kbB;
    const u32 braw1 = (u32)(rB1 * 640) + kbB;

    // per-lane biases: channel ch = 8T+q, gates i,f,o,g
    const int ch = 8 * T + q;
    const float bI = conv_b[ch], bF = conv_b[32 + ch];
    const float bO = conv_b[64 + ch], bG = conv_b[96 + ch];

    // copy-phase constants: thread covers (n2 in own half, u = tid&3)
    const int n2c = half * 64 + (tid_h >> 2), ucp = tid & 3;
    const int pyc = (n2c >> 2) & 3, pxc = n2c & 3;
    const int hrow_base = (n2c >> 4) << 4;     // bb*16

    float cst[8];
    #pragma unroll
    for (int i = 0; i < 8; i++) cst[i] = 0.0f;

    float* hfin = (float*)(smc + HFIN_OFF);    // [512][8], dedicated region

    __syncthreads();

    // ---- one-time stagger: half 1 waits until half 0 finished t=0 mma ----
    if (half == 1)
        asm volatile("bar.sync 3, 512;" ::: "memory");

    const int mybar = 1 + half;

    // ---------------------- 12-step recurrence (per-half) ----------------------
    #pragma unroll 1
    for (int t = 0; t < 12; ++t) {
        float accA[4][4], accB[4][4];          // [nf][d]; frag0 (i,f), frag1 (o,g)
        #pragma unroll
        for (int nf = 0; nf < 4; nf++) {
            accA[nf][0] = bI; accA[nf][1] = bI; accA[nf][2] = bF; accA[nf][3] = bF;
            accB[nf][0] = bO; accB[nf][1] = bO; accB[nf][2] = bG; accB[nf][3] = bG;
        }

        #pragma unroll 2
        for (int s = 0; s < 20; ++s) {
            const u32 so = (u32)(s * 32);
            u32 a0,a1,a2,a3, a4,a5,a6,a7, p0,p1,p2,p3, p4,p5,p6,p7;
            ldsm4(a0,a1,a2,a3, sb + AHI_OFF + sw640(araw0 + so));
            ldsm4(a4,a5,a6,a7, sb + AHI_OFF + sw640(araw1 + so));
            ldsm4(p0,p1,p2,p3, sb + BHI_OFF + sw640(braw0 + so));
            ldsm4(p4,p5,p6,p7, sb + BHI_OFF + sw640(braw1 + so));
            mma16816(accA[0], a0,a1,a2,a3, p0,p1);
            mma16816(accA[1], a0,a1,a2,a3, p2,p3);
            mma16816(accA[2], a0,a1,a2,a3, p4,p5);
            mma16816(accA[3], a0,a1,a2,a3, p6,p7);
            mma16816(accB[0], a4,a5,a6,a7, p0,p1);
            mma16816(accB[1], a4,a5,a6,a7, p2,p3);
            mma16816(accB[2], a4,a5,a6,a7, p4,p5);
            mma16816(accB[3], a4,a5,a6,a7, p6,p7);
        }

        // release half 1 after half 0's first mma phase (non-blocking arrive)
        if (t == 0 && half == 0)
            asm volatile("bar.arrive 3, 512;" ::: "memory");

        barh(mybar);   // own half's ldsm reads done

        // ---- LSTM cell (in-lane) -> h-compact (or hfin at t=11) ----
        #pragma unroll
        for (int nf = 0; nf < 4; nf++) {
            #pragma unroll
            for (int cc = 0; cc < 2; cc++) {
                float gi = accA[nf][cc],     gf = accA[nf][2 + cc];
                float go = accB[nf][cc],     gg = accB[nf][2 + cc];
                const int ci = nf * 2 + cc;
                float c = sigf(gf) * cst[ci] + sigf(gi) * tanh_fast(gg);
                cst[ci] = c;
                float h = sigf(go) * tanh_fast(c);

                const int n = half * 64 + nhl * 32 + nf * 8 + 2 * j + cc;
                if (t < 11) {
                    u32 myh = (u32)__half_as_ushort(__float2half(h));
                    u32 oth = __shfl_down_sync(0xFFFFFFFFu, myh, 4);
                    if ((q & 1) == 0)      // ch even: pack (ch, ch+1)
                        *(u32*)(smc + HC_OFF + n * 64 + ch * 2) = myh | (oth << 16);
                } else {
                    hfin[(ch * 16 + (n & 15)) * 8 + (n >> 4)] = h;
                }
            }
        }

        if (t < 11) {
            barh(mybar);   // own half's h-compact ready

            // ---- vector copy: B[n2][tap*32 .. +32) = hc[nsrc][0..32) ----
            #pragma unroll
            for (int tap = 0; tap < 9; tap++) {
                const int dy = tap / 3 - 1, dx = tap % 3 - 1;
                const int sy = pyc + dy, sx = pxc + dx;
                if (sy >= 0 && sy < 4 && sx >= 0 && sx < 4) {
                    const int nsrc = hrow_base + (sy << 2) + sx;
                    uint4 v = *(const uint4*)(smc + HC_OFF + nsrc * 64 + ucp * 16);
                    *(uint4*)(smc + BHI_OFF +
                              sw640((u32)(n2c * 640 + tap * 64 + ucp * 16))) = v;
                }
            }

            // x scatter for t+1 (own half's rows only)
            if (tid_h < 192) {
                int bb = half * 4 + tid_h / 48, m = tid_h % 48;
                int xc = m >> 4, sy2 = (m >> 2) & 3, sx2 = m & 3;
                u16 hv = xs[(t + 1) * 384 + bb * 48 + m];
                #pragma unroll
                for (int dy = 0; dy < 3; dy++) {
                    int ny = sy2 + 1 - dy; if (ny < 0 || ny > 3) continue;
                    #pragma unroll
                    for (int dx = 0; dx < 3; dx++) {
                        int nx = sx2 + 1 - dx; if (nx < 0 || nx > 3) continue;
                        int k = 288 + (dy * 3 + dx) * 3 + xc;
                        int nn = bb * 16 + ny * 4 + nx;
                        *(u16*)(smc + BHI_OFF + sw640((u32)(nn * 640 + k * 2))) = hv;
                    }
                }
            }
            barh(mybar);   // own half's B ready for next mma
        }
    }

    __syncthreads();           // both halves done; hfin visible to all

    // ------------------------------ decoder ------------------------------
    float* hf_s = (float*)(smc + HF_OFF);                 // [8][32]
    float* z1   = (float*)(smc + BHI_OFF);                // [256][8] (B dead)
    float* z2   = (float*)(smc + BHI_OFF + 8192);         // [128][8]
    const int db = tid >> 6, dt = tid & 63;
    const int gb = b0 + db;
    const int gld = (gb < B) ? gb : (B - 1);

    if (dt < 32) {
        float hv = hour[gld];
        float a = he_b2[dt];
        #pragma unroll
        for (int k2 = 0; k2 < 16; ++k2) {
            float tt = fmaxf(hv * he_w1[k2] + he_b1[k2], 0.0f);
            a += tt * he_w2[k2 * 32 + dt];
        }
        hf_s[db * 32 + dt] = a;
    }
    __syncthreads();

    // L1: 544 -> 256, 4 outputs/thread
    {
        const int j0 = dt * 4;
        float a0 = d_b1[j0], a1 = d_b1[j0 + 1], a2 = d_b1[j0 + 2], a3 = d_b1[j0 + 3];
        #pragma unroll 4
        for (int i = 0; i < 512; ++i) {
            float zi = hfin[i * 8 + db];
            float4 w4 = *(const float4*)(d_w1 + i * 256 + j0);
            a0 += zi * w4.x; a1 += zi * w4.y; a2 += zi * w4.z; a3 += zi * w4.w;
        }
        #pragma unroll 4
        for (int i = 0; i < 32; ++i) {
            float zi = hf_s[db * 32 + i];
            float4 w4 = *(const float4*)(d_w1 + (512 + i) * 256 + j0);
            a0 += zi * w4.x; a1 += zi * w4.y; a2 += zi * w4.z; a3 += zi * w4.w;
        }
        z1[(j0 + 0) * 8 + db] = fmaxf(a0, 0.0f);
        z1[(j0 + 1) * 8 + db] = fmaxf(a1, 0.0f);
        z1[(j0 + 2) * 8 + db] = fmaxf(a2, 0.0f);
        z1[(j0 + 3) * 8 + db] = fmaxf(a3, 0.0f);
    }
    __syncthreads();

    // L2: 256 -> 128, 2 outputs/thread
    {
        const int j0 = dt * 2;
        float a0 = d_b2[j0], a1 = d_b2[j0 + 1];
        #pragma unroll 4
        for (int i = 0; i < 256; ++i) {
            float zi = z1[i * 8 + db];
            float2 w2 = *(const float2*)(d_w2 + i * 128 + j0);
            a0 += zi * w2.x; a1 += zi * w2.y;
        }
        z2[(j0 + 0) * 8 + db] = fmaxf(a0, 0.0f);
        z2[(j0 + 1) * 8 + db] = fmaxf(a1, 0.0f);
    }
    __syncthreads();

    // L3: 128 -> 30 + sigmoid
    if (dt < 30 && gb < B) {
        float a = d_b3[dt];
        #pragma unroll 4
        for (int i = 0; i < 128; ++i)
            a += z2[i * 8 + db] * d_w3[i * 30 + dt];
        out[(size_t)gb * 30 + dt] = sigf(a);
    }
}

extern "C" void kernel_launch(void* const* d_in, const int* in_sizes, int n_in,
                              void* d_out, int out_size)
{
    const float* x      = (const float*)d_in[0];
    const float* hour   = (const float*)d_in[1];
    const float* conv_w = (const float*)d_in[2];
    const float* conv_b = (const float*)d_in[3];
    const float* he_w1  = (const float*)d_in[4];
    const float* he_b1  = (const float*)d_in[5];
    const float* he_w2  = (const float*)d_in[6];
    const float* he_b2  = (const float*)d_in[7];
    const float* d_w1   = (const float*)d_in[8];
    const float* d_b1   = (const float*)d_in[9];
    const float* d_w2   = (const float*)d_in[10];
    const float* d_b2   = (const float*)d_in[11];
    const float* d_w3   = (const float*)d_in[12];
    const float* d_b3   = (const float*)d_in[13];

    const int B    = in_sizes[0] / 576;
    const int grid = (B + NB - 1) / NB;

    cudaFuncSetAttribute(wq_hmma5_kernel,
                         cudaFuncAttributeMaxDynamicSharedMemorySize, SMEM_TOT);

    wq_hmma5_kernel<<<grid, NTHR, SMEM_TOT>>>(x, hour, conv_w, conv_b,
                                              he_w1, he_b1, he_w2, he_b2,
                                              d_w1, d_b1, d_w2, d_b2, d_w3, d_b3,
                                              (float*)d_out, B);
}

// round 13
// speedup vs baseline: 1.1555x; 1.0979x over previous
#include <cuda_runtime.h>
#include <cuda_fp16.h>

// ---------------------------------------------------------------------------
// R13: HMMA ConvLSTM, fp16, NB=8, phase-shifted half-CTAs.
// B im2col ELIMINATED: h stored once as rows h[n][32ch] (pitch 80B); each
// tap's B-fragment loaded via per-lane-addressed ldmatrix with row shift
// n + (dy*4+dx), invalid rows -> shared zero row. x-part via small Bx tile
// (identity rows), rebuilt per step in the cell phase.
// Warp (half,T,nhl): A-rows [32T,+32) x n-cols [64*half+32*nhl,+32).
// A row perm: R = 32T + 8g + q <-> oc = g*32 + (8T+q): LSTM fully in-lane.
// Activations: tanh.approx.f32 (sigmoid = 0.5 + 0.5*tanh(v/2)).
// ---------------------------------------------------------------------------

typedef unsigned int u32;
typedef unsigned short u16;

#define NTHR 512
#define NB   8

#define AHI_OFF  0           // 128 x 640B = 81920 (alias: z1/z2 after loop)
#define H_OFF    81920       // 129 rows x 80B = 10320 (pad 10400); row 128 = zeros
#define BX_OFF   92320       // 128 x 80B = 10240
#define XS_OFF   102560      // 12*8*48 u16 = 9216
#define HF_OFF   111776      // 8*32 f32 = 1024
#define HFIN_OFF 112800      // [512][8] f32 = 16384
#define SMEM_TOT 129184

static __device__ __forceinline__ u32 sw640(u32 b) { return b ^ ((b >> 3) & 0x70); }

static __device__ __forceinline__ u32 smem_u32(const void* p) {
    u32 a;
    asm("{ .reg .u64 t; cvta.to.shared.u64 t, %1; cvt.u32.u64 %0, t; }" : "=r"(a) : "l"(p));
    return a;
}
static __device__ __forceinline__ float tanh_a(float v) {
    float r;
    asm("tanh.approx.f32 %0, %1;" : "=f"(r) : "f"(v));
    return r;
}
static __device__ __forceinline__ float sig_a(float v) {
    return fmaf(tanh_a(0.5f * v), 0.5f, 0.5f);
}
static __device__ __forceinline__ float sigf(float v) {
    return __fdividef(1.0f, 1.0f + __expf(-v));
}
static __device__ __forceinline__ void ldsm4(u32& r0, u32& r1, u32& r2, u32& r3, u32 a) {
    asm volatile("ldmatrix.sync.aligned.m8n8.x4.shared.b16 {%0,%1,%2,%3}, [%4];"
        : "=r"(r0), "=r"(r1), "=r"(r2), "=r"(r3) : "r"(a));
}
static __device__ __forceinline__ void mma16816(float* d, u32 a0, u32 a1, u32 a2, u32 a3,
                                                u32 b0, u32 b1) {
    asm volatile("mma.sync.aligned.m16n8k16.row.col.f32.f16.f16.f32 "
        "{%0,%1,%2,%3}, {%4,%5,%6,%7}, {%8,%9}, {%0,%1,%2,%3};"
        : "+f"(d[0]), "+f"(d[1]), "+f"(d[2]), "+f"(d[3])
        : "r"(a0), "r"(a1), "r"(a2), "r"(a3), "r"(b0), "r"(b1));
}
static __device__ __forceinline__ void barh(int id) {
    asm volatile("bar.sync %0, 256;" :: "r"(id) : "memory");
}

extern __shared__ char smc[];

__global__ __launch_bounds__(NTHR, 1)
void wq_hmma6_kernel(const float* __restrict__ x,      const float* __restrict__ hour,
                     const float* __restrict__ conv_w, const float* __restrict__ conv_b,
                     const float* __restrict__ he_w1,  const float* __restrict__ he_b1,
                     const float* __restrict__ he_w2,  const float* __restrict__ he_b2,
                     const float* __restrict__ d_w1,   const float* __restrict__ d_b1,
                     const float* __restrict__ d_w2,   const float* __restrict__ d_b2,
                     const float* __restrict__ d_w3,   const float* __restrict__ d_b3,
                     float* __restrict__ out, int B)
{
    const int tid  = threadIdx.x;
    const int w    = tid >> 5, lane = tid & 31;
    const int half = w >> 3;
    const int wh   = w & 7;
    const int T    = wh >> 1, nhl = wh & 1;
    const int q    = lane >> 2, j = lane & 3;
    const int b0   = blockIdx.x * NB;
    const int tid_h = tid & 255;
    const u32 sb   = smem_u32(smc);
    u16* xs = (u16*)(smc + XS_OFF);

    // ---------------- prologue ----------------
    {   // zero h (incl. zero row) + Bx : contiguous 20640 B = 5160 u32
        u32* bz = (u32*)(smc + H_OFF);
        for (int e = tid; e < 5160; e += NTHR) bz[e] = 0u;
    }
    for (int e = tid; e < 12 * NB * 48; e += NTHR) {       // 4608
        int t = e / 384, rm = e - t * 384;
        int bb = rm / 48, qq = rm - bb * 48;
        int gb = b0 + bb; if (gb >= B) gb = B - 1;
        xs[e] = __half_as_ushort(__float2half(x[(size_t)gb * 576 + t * 48 + qq]));
    }
    for (int e = tid; e < 128 * 320; e += NTHR) {          // A build: 80/thread
        int R = e / 320, k = e - R * 320;
        int g = (R >> 3) & 3, TT = R >> 5, qq = R & 7;
        int oc = g * 32 + TT * 8 + qq;
        float wv = 0.0f;
        if (k < 288)      wv = conv_w[oc * 315 + (3 + (k & 31)) * 9 + (k >> 5)];
        else if (k < 315) { int m = k - 288; wv = conv_w[oc * 315 + (m % 3) * 9 + (m / 3)]; }
        *(u16*)(smc + AHI_OFF + sw640((u32)(R * 640 + k * 2))) =
            __half_as_ushort(__float2half(wv));
    }
    __syncthreads();

    // Bx scatter for t=0: Bx[n2][tap*3+xc]
    if (tid < NB * 48) {
        int bb = tid / 48, m = tid - bb * 48;
        int xc = m >> 4, sy = (m >> 2) & 3, sx = m & 3;
        u16 hv = xs[bb * 48 + m];
        #pragma unroll
        for (int dy = 0; dy < 3; dy++) {
            int ny = sy + 1 - dy; if (ny < 0 || ny > 3) continue;
            #pragma unroll
            for (int dx = 0; dx < 3; dx++) {
                int nx = sx + 1 - dx; if (nx < 0 || nx > 3) continue;
                int kl = (dy * 3 + dx) * 3 + xc;
                int n2 = bb * 16 + ny * 4 + nx;
                *(u16*)(smc + BX_OFF + n2 * 80 + kl * 2) = hv;
            }
        }
    }

    // ---- per-lane A addresses (swizzled pitch 640) ----
    const u32 araw0 = (u32)((32 * T + (lane & 7) + ((lane >> 3) & 1) * 8) * 640
                            + ((lane >> 4) & 1) * 16);
    const u32 araw1 = araw0 + 16 * 640;

    // ---- per-lane B row bases (pitch 80, no swizzle) ----
    const int seg  = (lane >> 3) & 1;                 // 16B k-segment within ldsm
    const int nl1  = half * 64 + 32 * nhl + (lane & 7) + ((lane >> 4) & 1) * 8;
    const int nl2  = nl1 + 16;
    const int hb1  = (int)(sb + H_OFF) + nl1 * 80 + seg * 16;
    const int hb2  = (int)(sb + H_OFF) + nl2 * 80 + seg * 16;
    const int zb   = (int)(sb + H_OFF) + 128 * 80 + seg * 16;
    const int xb1  = (int)(sb + BX_OFF) + nl1 * 80 + seg * 16;
    const int xb2  = (int)(sb + BX_OFF) + nl2 * 80 + seg * 16;

    // validity masks: bit tap set iff shifted pixel in-bounds for this row
    u32 vm1 = 0, vm2 = 0;
    {
        int py1 = (nl1 >> 2) & 3, px1 = nl1 & 3;
        int py2 = (nl2 >> 2) & 3, px2 = nl2 & 3;
        #pragma unroll
        for (int tap = 0; tap < 9; tap++) {
            int dy = tap / 3 - 1, dx = tap % 3 - 1;
            if ((u32)(py1 + dy) < 4u && (u32)(px1 + dx) < 4u) vm1 |= 1u << tap;
            if ((u32)(py2 + dy) < 4u && (u32)(px2 + dx) < 4u) vm2 |= 1u << tap;
        }
    }

    // per-lane biases: channel ch = 8T+q, gates i,f,o,g
    const int ch = 8 * T + q;
    const float bI = conv_b[ch], bF = conv_b[32 + ch];
    const float bO = conv_b[64 + ch], bG = conv_b[96 + ch];

    float cst[8];
    #pragma unroll
    for (int i = 0; i < 8; i++) cst[i] = 0.0f;

    float* hfin = (float*)(smc + HFIN_OFF);

    __syncthreads();

    // ---- one-time stagger: half 1 waits until half 0 finished t=0 mma ----
    if (half == 1)
        asm volatile("bar.sync 3, 512;" ::: "memory");

    const int mybar = 1 + half;

    // ---------------------- 12-step recurrence (per-half) ----------------------
    #pragma unroll 1
    for (int t = 0; t < 12; ++t) {
        float accA[4][4], accB[4][4];
        #pragma unroll
        for (int nf = 0; nf < 4; nf++) {
            accA[nf][0] = bI; accA[nf][1] = bI; accA[nf][2] = bF; accA[nf][3] = bF;
            accB[nf][0] = bO; accB[nf][1] = bO; accB[nf][2] = bG; accB[nf][3] = bG;
        }

        // 9 h-taps + 1 x-tap, 2 k-halves each
        #pragma unroll
        for (int tap = 0; tap < 10; ++tap) {
            int bA, bB;
            if (tap < 9) {
                const int doff = ((tap / 3 - 1) * 4 + (tap % 3 - 1)) * 80;
                bA = ((vm1 >> tap) & 1) ? hb1 + doff : zb;
                bB = ((vm2 >> tap) & 1) ? hb2 + doff : zb;
            } else {
                bA = xb1; bB = xb2;
            }
            #pragma unroll
            for (int kh = 0; kh < 2; ++kh) {
                const u32 so = (u32)(tap * 64 + kh * 32);
                u32 a0,a1,a2,a3, a4,a5,a6,a7, p0,p1,p2,p3, p4,p5,p6,p7;
                ldsm4(a0,a1,a2,a3, sb + AHI_OFF + sw640(araw0 + so));
                ldsm4(a4,a5,a6,a7, sb + AHI_OFF + sw640(araw1 + so));
                ldsm4(p0,p1,p2,p3, (u32)(bA + kh * 32));
                ldsm4(p4,p5,p6,p7, (u32)(bB + kh * 32));
                mma16816(accA[0], a0,a1,a2,a3, p0,p1);
                mma16816(accA[1], a0,a1,a2,a3, p2,p3);
                mma16816(accA[2], a0,a1,a2,a3, p4,p5);
                mma16816(accA[3], a0,a1,a2,a3, p6,p7);
                mma16816(accB[0], a4,a5,a6,a7, p0,p1);
                mma16816(accB[1], a4,a5,a6,a7, p2,p3);
                mma16816(accB[2], a4,a5,a6,a7, p4,p5);
                mma16816(accB[3], a4,a5,a6,a7, p6,p7);
            }
        }

        if (t == 0 && half == 0)
            asm volatile("bar.arrive 3, 512;" ::: "memory");

        barh(mybar);   // own half's ldsm reads done

        // ---- LSTM cell (in-lane) -> h rows (or hfin at t=11) ----
        #pragma unroll
        for (int nf = 0; nf < 4; nf++) {
            #pragma unroll
            for (int cc = 0; cc < 2; cc++) {
                float gi = accA[nf][cc],     gf = accA[nf][2 + cc];
                float go = accB[nf][cc],     gg = accB[nf][2 + cc];
                const int ci = nf * 2 + cc;
                float c = sig_a(gf) * cst[ci] + sig_a(gi) * tanh_a(gg);
                cst[ci] = c;
                float h = sig_a(go) * tanh_a(c);

                const int n = half * 64 + nhl * 32 + nf * 8 + 2 * j + cc;
                if (t < 11) {
                    u32 myh = (u32)__half_as_ushort(__float2half(h));
                    u32 oth = __shfl_down_sync(0xFFFFFFFFu, myh, 4);
                    if ((q & 1) == 0)      // ch even: pack (ch, ch+1)
                        *(u32*)(smc + H_OFF + n * 80 + ch * 2) = myh | (oth << 16);
                } else {
                    hfin[(ch * 16 + (n & 15)) * 8 + (n >> 4)] = h;
                }
            }
        }

        if (t < 11) {
            // Bx scatter for t+1 (own half's rows only)
            if (tid_h < 192) {
                int bb = half * 4 + tid_h / 48, m = tid_h % 48;
                int xc = m >> 4, sy2 = (m >> 2) & 3, sx2 = m & 3;
                u16 hv = xs[(t + 1) * 384 + bb * 48 + m];
                #pragma unroll
                for (int dy = 0; dy < 3; dy++) {
                    int ny = sy2 + 1 - dy; if (ny < 0 || ny > 3) continue;
                    #pragma unroll
                    for (int dx = 0; dx < 3; dx++) {
                        int nx = sx2 + 1 - dx; if (nx < 0 || nx > 3) continue;
                        int kl = (dy * 3 + dx) * 3 + xc;
                        int nn = bb * 16 + ny * 4 + nx;
                        *(u16*)(smc + BX_OFF + nn * 80 + kl * 2) = hv;
                    }
                }
            }
            barh(mybar);   // h + Bx ready for next mma
        }
    }

    __syncthreads();           // both halves done; hfin visible

    // ------------------------------ decoder ------------------------------
    float* hf_s = (float*)(smc + HF_OFF);                 // [8][32]
    float* z1   = (float*)(smc + AHI_OFF);                // [256][8] (A dead)
    float* z2   = (float*)(smc + AHI_OFF + 8192);         // [128][8]
    const int db = tid >> 6, dt = tid & 63;
    const int gb = b0 + db;
    const int gld = (gb < B) ? gb : (B - 1);

    if (dt < 32) {
        float hv = hour[gld];
        float a = he_b2[dt];
        #pragma unroll
        for (int k2 = 0; k2 < 16; ++k2) {
            float tt = fmaxf(hv * he_w1[k2] + he_b1[k2], 0.0f);
            a += tt * he_w2[k2 * 32 + dt];
        }
        hf_s[db * 32 + dt] = a;
    }
    __syncthreads();

    // L1: 544 -> 256, 4 outputs/thread
    {
        const int j0 = dt * 4;
        float a0 = d_b1[j0], a1 = d_b1[j0 + 1], a2 = d_b1[j0 + 2], a3 = d_b1[j0 + 3];
        #pragma unroll 4
        for (int i = 0; i < 512; ++i) {
            float zi = hfin[i * 8 + db];
            float4 w4 = *(const float4*)(d_w1 + i * 256 + j0);
            a0 += zi * w4.x; a1 += zi * w4.y; a2 += zi * w4.z; a3 += zi * w4.w;
        }
        #pragma unroll 4
        for (int i = 0; i < 32; ++i) {
            float zi = hf_s[db * 32 + i];
            float4 w4 = *(const float4*)(d_w1 + (512 + i) * 256 + j0);
            a0 += zi * w4.x; a1 += zi * w4.y; a2 += zi * w4.z; a3 += zi * w4.w;
        }
        z1[(j0 + 0) * 8 + db] = fmaxf(a0, 0.0f);
        z1[(j0 + 1) * 8 + db] = fmaxf(a1, 0.0f);
        z1[(j0 + 2) * 8 + db] = fmaxf(a2, 0.0f);
        z1[(j0 + 3) * 8 + db] = fmaxf(a3, 0.0f);
    }
    __syncthreads();

    // L2: 256 -> 128, 2 outputs/thread
    {
        const int j0 = dt * 2;
        float a0 = d_b2[j0], a1 = d_b2[j0 + 1];
        #pragma unroll 4
        for (int i = 0; i < 256; ++i) {
            float zi = z1[i * 8 + db];
            float2 w2 = *(const float2*)(d_w2 + i * 128 + j0);
            a0 += zi * w2.x; a1 += zi * w2.y;
        }
        z2[(j0 + 0) * 8 + db] = fmaxf(a0, 0.0f);
        z2[(j0 + 1) * 8 + db] = fmaxf(a1, 0.0f);
    }
    __syncthreads();

    // L3: 128 -> 30 + sigmoid (precise)
    if (dt < 30 && gb < B) {
        float a = d_b3[dt];
        #pragma unroll 4
        for (int i = 0; i < 128; ++i)
            a += z2[i * 8 + db] * d_w3[i * 30 + dt];
        out[(size_t)gb * 30 + dt] = sigf(a);
    }
}

extern "C" void kernel_launch(void* const* d_in, const int* in_sizes, int n_in,
                              void* d_out, int out_size)
{
    const float* x      = (const float*)d_in[0];
    const float* hour   = (const float*)d_in[1];
    const float* conv_w = (const float*)d_in[2];
    const float* conv_b = (const float*)d_in[3];
    const float* he_w1  = (const float*)d_in[4];
    const float* he_b1  = (const float*)d_in[5];
    const float* he_w2  = (const float*)d_in[6];
    const float* he_b2  = (const float*)d_in[7];
    const float* d_w1   = (const float*)d_in[8];
    const float* d_b1   = (const float*)d_in[9];
    const float* d_w2   = (const float*)d_in[10];
    const float* d_b2   = (const float*)d_in[11];
    const float* d_w3   = (const float*)d_in[12];
    const float* d_b3   = (const float*)d_in[13];

    const int B    = in_sizes[0] / 576;
    const int grid = (B + NB - 1) / NB;

    cudaFuncSetAttribute(wq_hmma6_kernel,
                         cudaFuncAttributeMaxDynamicSharedMemorySize, SMEM_TOT);

    wq_hmma6_kernel<<<grid, NTHR, SMEM_TOT>>>(x, hour, conv_w, conv_b,
                                              he_w1, he_b1, he_w2, he_b2,
                                              d_w1, d_b1, d_w2, d_b2, d_w3, d_b3,
                                              (float*)d_out, B);
}